// round 11
// baseline (speedup 1.0000x reference)
#include <cuda_runtime.h>
#include <cuda_fp16.h>
#include <math.h>

#define NN   50000
#define EE   1600000
#define DIN  128
#define HIDD 128
#define DOUT 64
#define NLL  200000
#define NEG  0.2f

#define SCAN_B 512
#define NBLK   ((NN + SCAN_B - 1) / SCAN_B)   // 98
#define GEMM_BLOCKS ((NN + 127) / 128)        // 391
#define E4_BLOCKS   ((EE / 4 + 255) / 256)    // 1563
#define FIN_BLOCKS  ((NN + 255) / 256)        // 196
#define DEC_BLOCKS  (((NLL + 3) / 4 * 32 + 255) / 256)
#define ZERO_BLOCKS 32

// ---------------- scratch (device globals; no allocation allowed) ----------------
__device__ float  g_bufA[NN * HIDD];
__device__ float  g_bufB[NN * HIDD];
__device__ __half g_h16[NN * HIDD];    // fp16 shadow of current GEMM output (gather source)
__device__ float  g_zbuf[NN * DOUT];
__device__ float  g_as[NN];
__device__ float  g_ad[NN];
__device__ float  g_dinv[NN];
__device__ int    g_deg[NN];       // zero-initialized at load; re-zeroed by decode
__device__ int    g_cursor[NN];    // same
__device__ int    g_rowloc[NN];    // block-local exclusive scan
__device__ int    g_rowptr[NN + 1];
__device__ int    g_csrc[EE];
__device__ int    g_bsum[NBLK];

__device__ __forceinline__ float lrelu(float v) { return v > 0.f ? v : NEG * v; }

// packed f32x2 helpers
__device__ __forceinline__ unsigned long long pack2(float lo, float hi) {
    unsigned long long r;
    asm("mov.b64 %0, {%1, %2};" : "=l"(r) : "f"(lo), "f"(hi));
    return r;
}
__device__ __forceinline__ void unpack2(unsigned long long v, float& lo, float& hi) {
    asm("mov.b64 {%0, %1}, %2;" : "=f"(lo), "=f"(hi) : "l"(v));
}
__device__ __forceinline__ void fma2(unsigned long long& d,
                                     unsigned long long a, unsigned long long b) {
    asm("fma.rn.f32x2 %0, %1, %2, %0;" : "+l"(d) : "l"(a), "l"(b));
}

// ---------------- launch 1: per-block local scan (+bsum, +dinv) ----------------
__global__ void scan_partial_kernel() {
    __shared__ int ws[SCAN_B / 32];
    int tid = threadIdx.x;
    int lane = tid & 31, wid = tid >> 5;
    int i = blockIdx.x * SCAN_B + tid;
    int v = (i < NN) ? g_deg[i] : 0;
    if (i < NN) g_dinv[i] = rsqrtf((float)(v + 1));
    int x = v;
    #pragma unroll
    for (int o = 1; o < 32; o <<= 1) {
        int y = __shfl_up_sync(0xffffffffu, x, o);
        if (lane >= o) x += y;
    }
    if (lane == 31) ws[wid] = x;
    __syncthreads();
    if (tid < 32) {
        int w = (tid < SCAN_B / 32) ? ws[tid] : 0;
        #pragma unroll
        for (int o = 1; o < SCAN_B / 32; o <<= 1) {
            int y = __shfl_up_sync(0xffffffffu, w, o);
            if (tid >= o) w += y;
        }
        if (tid < SCAN_B / 32) ws[tid] = w;
    }
    __syncthreads();
    int pref = wid ? ws[wid - 1] : 0;
    int incl = x + pref;
    if (i < NN) g_rowloc[i] = incl - v;
    if (tid == SCAN_B - 1) g_bsum[blockIdx.x] = incl;
}

__device__ __forceinline__ void block_boff(int* s_boff, int* s_ws) {
    int tid = threadIdx.x;
    if (tid < 128) {
        int lane = tid & 31, w4 = tid >> 5;
        int v = (tid < NBLK) ? g_bsum[tid] : 0;
        int x = v;
        #pragma unroll
        for (int o = 1; o < 32; o <<= 1) {
            int y = __shfl_up_sync(0xffffffffu, x, o);
            if (lane >= o) x += y;
        }
        if (lane == 31) s_ws[w4] = x;
    }
    __syncthreads();
    if (tid < 32) {
        int w = (tid < 4) ? s_ws[tid] : 0;
        #pragma unroll
        for (int o = 1; o < 4; o <<= 1) {
            int y = __shfl_up_sync(0xffffffffu, w, o);
            if (tid >= o) w += y;
        }
        if (tid < 4) s_ws[tid] = w;
    }
    __syncthreads();
    if (tid < 128) {
        int lane = tid & 31, w4 = tid >> 5;
        int v = (tid < NBLK) ? g_bsum[tid] : 0;
        int x = v;
        #pragma unroll
        for (int o = 1; o < 32; o <<= 1) {
            int y = __shfl_up_sync(0xffffffffu, x, o);
            if (lane >= o) x += y;
        }
        int pref = w4 ? s_ws[w4 - 1] : 0;
        if (tid < NBLK) s_boff[tid] = x + pref - v;
    }
    __syncthreads();
}

// ---------------- launch 2: CSR fill + rowptr finalize ----------------
__global__ void fill_finalize_kernel(const int* __restrict__ src, const int* __restrict__ dst) {
    __shared__ int s_boff[NBLK];
    __shared__ int s_ws[4];
    block_boff(s_boff, s_ws);
    int tid = threadIdx.x;
    int b = blockIdx.x;
    if (b < E4_BLOCKS) {
        int i = b * 256 + tid;
        if (i < EE / 4) {
            int4 s = reinterpret_cast<const int4*>(src)[i];
            int4 d = reinterpret_cast<const int4*>(dst)[i];
            int p;
            p = atomicAdd(&g_cursor[d.x], 1); g_csrc[g_rowloc[d.x] + s_boff[d.x >> 9] + p] = s.x;
            p = atomicAdd(&g_cursor[d.y], 1); g_csrc[g_rowloc[d.y] + s_boff[d.y >> 9] + p] = s.y;
            p = atomicAdd(&g_cursor[d.z], 1); g_csrc[g_rowloc[d.z] + s_boff[d.z >> 9] + p] = s.z;
            p = atomicAdd(&g_cursor[d.w], 1); g_csrc[g_rowloc[d.w] + s_boff[d.w >> 9] + p] = s.w;
        }
    } else {
        int i = (b - E4_BLOCKS) * 256 + tid;
        if (i < NN) g_rowptr[i] = g_rowloc[i] + s_boff[i >> 9];
        if (b == E4_BLOCKS && tid == 0) g_rowptr[NN] = EE;
    }
}

// ---------------- SGEMM (FFMA2) + fp16 shadow epilogue ----------------
template<int BN, bool FUSE, bool COUNT>
__global__ __launch_bounds__(256)
void sgemm128_kernel(const float* __restrict__ A, const float* __restrict__ B,
                     float* __restrict__ C,
                     const float* __restrict__ avs, const float* __restrict__ avd,
                     const int* __restrict__ edst) {
    if (COUNT && blockIdx.x >= GEMM_BLOCKS) {
        int bi = blockIdx.x - GEMM_BLOCKS;
        int i = bi * 256 + threadIdx.x;
        if (i < EE / 4) {
            int4 d = reinterpret_cast<const int4*>(edst)[i];
            atomicAdd(&g_deg[d.x], 1);
            atomicAdd(&g_deg[d.y], 1);
            atomicAdd(&g_deg[d.z], 1);
            atomicAdd(&g_deg[d.w], 1);
        }
        return;
    }
    constexpr int TN = BN / 16;
    constexpr int TN2 = TN / 2;
    __shared__ float As[16][132];
    __shared__ float Bs[16][BN];
    const int tid = threadIdx.x;
    const int block_row = blockIdx.x * 128;
    const int tr = tid >> 4;
    const int tc = tid & 15;

    unsigned long long acc2[8][TN2];
    #pragma unroll
    for (int i = 0; i < 8; i++)
        #pragma unroll
        for (int j = 0; j < TN2; j++) acc2[i][j] = 0ull;

    const int aRow = tid >> 2;
    const int aCol = (tid & 3) << 2;

    #pragma unroll 2
    for (int k0 = 0; k0 < 128; k0 += 16) {
        #pragma unroll
        for (int i = 0; i < 2; i++) {
            int r = aRow + i * 64;
            int grow = block_row + r;
            float4 v = make_float4(0.f, 0.f, 0.f, 0.f);
            if (grow < NN)
                v = *reinterpret_cast<const float4*>(&A[(size_t)grow * 128 + k0 + aCol]);
            As[aCol + 0][r] = v.x;
            As[aCol + 1][r] = v.y;
            As[aCol + 2][r] = v.z;
            As[aCol + 3][r] = v.w;
        }
        if (BN == 128) {
            #pragma unroll
            for (int i = 0; i < 2; i++) {
                int r = (tid >> 5) + i * 8;
                int c = (tid & 31) * 4;
                *reinterpret_cast<float4*>(&Bs[r][c]) =
                    *reinterpret_cast<const float4*>(&B[(size_t)(k0 + r) * BN + c]);
            }
        } else {
            int r = tid >> 4;
            int c = (tid & 15) * 4;
            *reinterpret_cast<float4*>(&Bs[r][c]) =
                *reinterpret_cast<const float4*>(&B[(size_t)(k0 + r) * BN + c]);
        }
        __syncthreads();
        #pragma unroll
        for (int kk = 0; kk < 16; kk++) {
            float ra[8], rb[TN];
            *reinterpret_cast<float4*>(&ra[0]) = *reinterpret_cast<float4*>(&As[kk][tr * 8]);
            *reinterpret_cast<float4*>(&ra[4]) = *reinterpret_cast<float4*>(&As[kk][tr * 8 + 4]);
            #pragma unroll
            for (int j4 = 0; j4 < TN / 4; j4++)
                *reinterpret_cast<float4*>(&rb[j4 * 4]) =
                    *reinterpret_cast<float4*>(&Bs[kk][tc * TN + j4 * 4]);
            unsigned long long bp[TN2];
            #pragma unroll
            for (int j = 0; j < TN2; j++) bp[j] = pack2(rb[2 * j], rb[2 * j + 1]);
            #pragma unroll
            for (int i = 0; i < 8; i++) {
                unsigned long long ap = pack2(ra[i], ra[i]);
                #pragma unroll
                for (int j = 0; j < TN2; j++)
                    fma2(acc2[i][j], ap, bp[j]);
            }
        }
        __syncthreads();
    }

    float acc[8][TN];
    #pragma unroll
    for (int i = 0; i < 8; i++)
        #pragma unroll
        for (int j = 0; j < TN2; j++)
            unpack2(acc2[i][j], acc[i][2 * j], acc[i][2 * j + 1]);

    #pragma unroll
    for (int i = 0; i < 8; i++) {
        int grow = block_row + tr * 8 + i;
        if (grow < NN) {
            #pragma unroll
            for (int j4 = 0; j4 < TN / 4; j4++) {
                float4 v = make_float4(acc[i][j4 * 4 + 0], acc[i][j4 * 4 + 1],
                                       acc[i][j4 * 4 + 2], acc[i][j4 * 4 + 3]);
                *reinterpret_cast<float4*>(&C[(size_t)grow * BN + tc * TN + j4 * 4]) = v;
            }
            // fp16 shadow (gather source for the agg kernels)
            __half2 hp[TN2];
            #pragma unroll
            for (int j = 0; j < TN2; j++)
                hp[j] = __floats2half2_rn(acc[i][2 * j], acc[i][2 * j + 1]);
            if (TN == 8)
                *reinterpret_cast<uint4*>(&g_h16[(size_t)grow * BN + tc * TN]) =
                    *reinterpret_cast<uint4*>(hp);
            else
                *reinterpret_cast<uint2*>(&g_h16[(size_t)grow * BN + tc * TN]) =
                    *reinterpret_cast<uint2*>(hp);
        }
    }

    if (FUSE) {
        float avsr[TN], avdr[TN];
        #pragma unroll
        for (int j = 0; j < TN; j++) {
            avsr[j] = avs[tc * TN + j];
            avdr[j] = avd[tc * TN + j];
        }
        #pragma unroll
        for (int i = 0; i < 8; i++) {
            float s = 0.f, d = 0.f;
            #pragma unroll
            for (int j = 0; j < TN; j++) {
                s = fmaf(acc[i][j], avsr[j], s);
                d = fmaf(acc[i][j], avdr[j], d);
            }
            #pragma unroll
            for (int mk = 1; mk < 16; mk <<= 1) {
                s += __shfl_xor_sync(0xffffffffu, s, mk);
                d += __shfl_xor_sync(0xffffffffu, d, mk);
            }
            if (tc == 0) {
                int grow = block_row + tr * 8 + i;
                if (grow < NN) { g_as[grow] = s; g_ad[grow] = d; }
            }
        }
    }
}

// ---------------- GAT aggregate: single fused pass, fp16 row gather ----------------
// Softmax shift-invariance: scores ~N(0,~2), no overflow risk without max-subtract.
__global__ __launch_bounds__(256)
void gat_agg_kernel(const float* __restrict__ bias,
                    float* __restrict__ out) {
    int warp = (blockIdx.x * blockDim.x + threadIdx.x) >> 5;
    int lane = threadIdx.x & 31;
    if (warp >= NN) return;
    int node = warp;
    int rs = g_rowptr[node], re = g_rowptr[node + 1];
    float adi = g_ad[node];
    float pself = __expf(lrelu(g_as[node] + adi));

    const uint2* h2 = reinterpret_cast<const uint2*>(g_h16);   // 4 halves per lane
    uint2 selfraw = h2[(size_t)node * 32 + lane];
    float2 sf01 = __half22float2(*reinterpret_cast<__half2*>(&selfraw.x));
    float2 sf23 = __half22float2(*reinterpret_cast<__half2*>(&selfraw.y));
    float4 acc = make_float4(pself * sf01.x, pself * sf01.y, pself * sf23.x, pself * sf23.y);
    float ssum_l = (lane == 0) ? pself : 0.f;

    for (int base = rs; base < re; base += 32) {
        int j = base + lane;
        int srcv = 0; float pv = 0.f;
        if (j < re) {
            srcv = g_csrc[j];
            pv = __expf(lrelu(g_as[srcv] + adi));
        }
        ssum_l += pv;
        int cnt = re - base;
        if (cnt >= 32) {
            #pragma unroll
            for (int t = 0; t < 32; t++) {
                int s = __shfl_sync(0xffffffffu, srcv, t);
                float p = __shfl_sync(0xffffffffu, pv, t);
                uint2 raw = h2[(size_t)s * 32 + lane];
                float2 f01 = __half22float2(*reinterpret_cast<__half2*>(&raw.x));
                float2 f23 = __half22float2(*reinterpret_cast<__half2*>(&raw.y));
                acc.x = fmaf(p, f01.x, acc.x);
                acc.y = fmaf(p, f01.y, acc.y);
                acc.z = fmaf(p, f23.x, acc.z);
                acc.w = fmaf(p, f23.y, acc.w);
            }
        } else {
            for (int t = 0; t < cnt; t++) {
                int s = __shfl_sync(0xffffffffu, srcv, t);
                float p = __shfl_sync(0xffffffffu, pv, t);
                uint2 raw = h2[(size_t)s * 32 + lane];
                float2 f01 = __half22float2(*reinterpret_cast<__half2*>(&raw.x));
                float2 f23 = __half22float2(*reinterpret_cast<__half2*>(&raw.y));
                acc.x = fmaf(p, f01.x, acc.x);
                acc.y = fmaf(p, f01.y, acc.y);
                acc.z = fmaf(p, f23.x, acc.z);
                acc.w = fmaf(p, f23.y, acc.w);
            }
        }
    }
    float ssum = ssum_l;
    #pragma unroll
    for (int o = 16; o; o >>= 1) ssum += __shfl_xor_sync(0xffffffffu, ssum, o);

    float inv = 1.f / ssum;
    float4 bv = reinterpret_cast<const float4*>(bias)[lane];
    float4 o;
    o.x = fmaxf(fmaf(acc.x, inv, bv.x), 0.f);
    o.y = fmaxf(fmaf(acc.y, inv, bv.y), 0.f);
    o.z = fmaxf(fmaf(acc.z, inv, bv.z), 0.f);
    o.w = fmaxf(fmaf(acc.w, inv, bv.w), 0.f);
    reinterpret_cast<float4*>(out)[(size_t)node * 32 + lane] = o;
}

// ---------------- GCN aggregate: fp16 gather (4 B/lane/edge), OUT=64 ----------------
__global__ __launch_bounds__(256)
void gcn_agg_kernel(const float* __restrict__ bias,
                    float* __restrict__ z) {
    int warp = (blockIdx.x * blockDim.x + threadIdx.x) >> 5;
    int lane = threadIdx.x & 31;
    if (warp >= NN) return;
    int node = warp;
    int rs = g_rowptr[node], re = g_rowptr[node + 1];
    float di = g_dinv[node];
    const unsigned int* h1 = reinterpret_cast<const unsigned int*>(g_h16); // 2 halves/lane
    unsigned int selfraw = h1[(size_t)node * 32 + lane];
    float2 gv = __half22float2(*reinterpret_cast<__half2*>(&selfraw));
    float nself = di * di;
    float2 acc = make_float2(nself * gv.x, nself * gv.y);
    for (int base = rs; base < re; base += 32) {
        int j = base + lane;
        int srcv = 0; float dv = 0.f;
        if (j < re) { srcv = g_csrc[j]; dv = g_dinv[srcv]; }
        int cnt = re - base;
        if (cnt >= 32) {
            #pragma unroll
            for (int t = 0; t < 32; t++) {
                int s = __shfl_sync(0xffffffffu, srcv, t);
                float nd = __shfl_sync(0xffffffffu, dv, t);
                float nrm = di * nd;
                unsigned int raw = h1[(size_t)s * 32 + lane];
                float2 v = __half22float2(*reinterpret_cast<__half2*>(&raw));
                acc.x = fmaf(nrm, v.x, acc.x);
                acc.y = fmaf(nrm, v.y, acc.y);
            }
        } else {
            for (int t = 0; t < cnt; t++) {
                int s = __shfl_sync(0xffffffffu, srcv, t);
                float nd = __shfl_sync(0xffffffffu, dv, t);
                float nrm = di * nd;
                unsigned int raw = h1[(size_t)s * 32 + lane];
                float2 v = __half22float2(*reinterpret_cast<__half2*>(&raw));
                acc.x = fmaf(nrm, v.x, acc.x);
                acc.y = fmaf(nrm, v.y, acc.y);
            }
        }
    }
    float2 bv = reinterpret_cast<const float2*>(bias)[lane];
    reinterpret_cast<float2*>(z)[(size_t)node * 32 + lane] =
        make_float2(acc.x + bv.x, acc.y + bv.y);
}

// ---------------- decode + re-zero of deg/cursor ----------------
__global__ void decode_kernel(const int* __restrict__ eli, float* __restrict__ out) {
    if (blockIdx.x >= DEC_BLOCKS) {
        int i = (blockIdx.x - DEC_BLOCKS) * 256 + threadIdx.x;
        for (int k = i; k < NN; k += ZERO_BLOCKS * 256) { g_deg[k] = 0; g_cursor[k] = 0; }
        return;
    }
    int gtid = blockIdx.x * blockDim.x + threadIdx.x;
    int warp = gtid >> 5;
    int lane = threadIdx.x & 31;
    int sub = lane >> 3, l8 = lane & 7;
    int e = warp * 4 + sub;
    if (e >= NLL) return;
    int a = eli[e];
    int b = eli[NLL + e];
    const float4* z4 = reinterpret_cast<const float4*>(g_zbuf);
    float4 va0 = z4[(size_t)a * 16 + l8];
    float4 va1 = z4[(size_t)a * 16 + 8 + l8];
    float4 vb0 = z4[(size_t)b * 16 + l8];
    float4 vb1 = z4[(size_t)b * 16 + 8 + l8];
    float dot = va0.x * vb0.x + va0.y * vb0.y + va0.z * vb0.z + va0.w * vb0.w
              + va1.x * vb1.x + va1.y * vb1.y + va1.z * vb1.z + va1.w * vb1.w;
    dot += __shfl_xor_sync(0xffffffffu, dot, 4);
    dot += __shfl_xor_sync(0xffffffffu, dot, 2);
    dot += __shfl_xor_sync(0xffffffffu, dot, 1);
    if (l8 == 0) out[e] = dot;
}

// ---------------- launch ----------------
extern "C" void kernel_launch(void* const* d_in, const int* in_sizes, int n_in,
                              void* d_out, int out_size) {
    const float* x   = (const float*)d_in[0];
    const int*   ei  = (const int*)d_in[1];          // [2,E]
    const int*   eli = (const int*)d_in[2];          // [2,NL]
    const float* W1  = (const float*)d_in[3];
    const float* a1s = (const float*)d_in[4];
    const float* a1d = (const float*)d_in[5];
    const float* b1  = (const float*)d_in[6];
    const float* W2  = (const float*)d_in[7];
    const float* a2s = (const float*)d_in[8];
    const float* a2d = (const float*)d_in[9];
    const float* b2  = (const float*)d_in[10];
    const float* W3  = (const float*)d_in[11];
    const float* a3s = (const float*)d_in[12];
    const float* a3d = (const float*)d_in[13];
    const float* b3  = (const float*)d_in[14];
    const float* W4  = (const float*)d_in[15];
    const float* b4  = (const float*)d_in[16];
    float* out = (float*)d_out;

    const int* e_src = ei;
    const int* e_dst = ei + EE;

    float *bufA, *bufB, *zbuf;
    cudaGetSymbolAddress((void**)&bufA, g_bufA);
    cudaGetSymbolAddress((void**)&bufB, g_bufB);
    cudaGetSymbolAddress((void**)&zbuf, g_zbuf);

    const int TB = 256;
    int node_warp_blocks = (NN * 32 + TB - 1) / TB;

    // 0: sgemm1 + fused degree-count
    sgemm128_kernel<HIDD, true, true><<<GEMM_BLOCKS + E4_BLOCKS, 256>>>(x, W1, bufA, a1s, a1d, e_dst);
    // 1: per-block local scan (+dinv, +bsum)
    scan_partial_kernel<<<NBLK, SCAN_B>>>();
    // 2: CSR fill + rowptr finalize
    fill_finalize_kernel<<<E4_BLOCKS + FIN_BLOCKS, TB>>>(e_src, e_dst);
    // 3: gat layer 1  <- profiled launch index
    gat_agg_kernel<<<node_warp_blocks, TB>>>(b1, bufB);

    // layer 2
    sgemm128_kernel<HIDD, true, false><<<GEMM_BLOCKS, 256>>>(bufB, W2, bufA, a2s, a2d, nullptr);
    gat_agg_kernel<<<node_warp_blocks, TB>>>(b2, bufB);

    // layer 3
    sgemm128_kernel<HIDD, true, false><<<GEMM_BLOCKS, 256>>>(bufB, W3, bufA, a3s, a3d, nullptr);
    gat_agg_kernel<<<node_warp_blocks, TB>>>(b3, bufB);

    // GCN
    sgemm128_kernel<DOUT, false, false><<<GEMM_BLOCKS, 256>>>(bufB, W4, bufA, nullptr, nullptr, nullptr);
    gcn_agg_kernel<<<node_warp_blocks, TB>>>(b4, zbuf);

    // decode + re-zero deg/cursor
    decode_kernel<<<DEC_BLOCKS + ZERO_BLOCKS, TB>>>(eli, out);
}

// round 12
// speedup vs baseline: 1.1456x; 1.1456x over previous
#include <cuda_runtime.h>
#include <cuda_fp16.h>
#include <math.h>

#define NN   50000
#define EE   1600000
#define DIN  128
#define HIDD 128
#define DOUT 64
#define NLL  200000
#define NEG  0.2f

#define SCAN_B 512
#define NBLK   ((NN + SCAN_B - 1) / SCAN_B)   // 98
#define GEMM_BLOCKS ((NN + 127) / 128)        // 391
#define E4_BLOCKS   ((EE / 4 + 255) / 256)    // 1563
#define FIN_BLOCKS  ((NN + 255) / 256)        // 196
#define DEC_BLOCKS  (((NLL + 3) / 4 * 32 + 255) / 256)
#define ZERO_BLOCKS 32

// ---------------- scratch (device globals; no allocation allowed) ----------------
__device__ float  g_bufB[NN * HIDD];   // agg output (fp32) = next GEMM input
__device__ __half g_h16[NN * HIDD];    // fp16 GEMM output (gather source; fp32 C is dead)
__device__ float  g_zbuf[NN * DOUT];
__device__ float  g_as[NN];
__device__ float  g_ad[NN];
__device__ float  g_dinv[NN];
__device__ int    g_deg[NN];       // zero-initialized at load; re-zeroed by decode
__device__ int    g_cursor[NN];    // same
__device__ int    g_rowloc[NN];    // block-local exclusive scan
__device__ int    g_rowptr[NN + 1];
__device__ int    g_csrc[EE];
__device__ int    g_bsum[NBLK];

__device__ __forceinline__ float lrelu(float v) { return v > 0.f ? v : NEG * v; }

// packed f32x2 helpers
__device__ __forceinline__ unsigned long long pack2(float lo, float hi) {
    unsigned long long r;
    asm("mov.b64 %0, {%1, %2};" : "=l"(r) : "f"(lo), "f"(hi));
    return r;
}
__device__ __forceinline__ void unpack2(unsigned long long v, float& lo, float& hi) {
    asm("mov.b64 {%0, %1}, %2;" : "=f"(lo), "=f"(hi) : "l"(v));
}
__device__ __forceinline__ void fma2(unsigned long long& d,
                                     unsigned long long a, unsigned long long b) {
    asm("fma.rn.f32x2 %0, %1, %2, %0;" : "+l"(d) : "l"(a), "l"(b));
}

// ---------------- launch 1: per-block local scan (+bsum, +dinv) ----------------
__global__ void scan_partial_kernel() {
    __shared__ int ws[SCAN_B / 32];
    int tid = threadIdx.x;
    int lane = tid & 31, wid = tid >> 5;
    int i = blockIdx.x * SCAN_B + tid;
    int v = (i < NN) ? g_deg[i] : 0;
    if (i < NN) g_dinv[i] = rsqrtf((float)(v + 1));
    int x = v;
    #pragma unroll
    for (int o = 1; o < 32; o <<= 1) {
        int y = __shfl_up_sync(0xffffffffu, x, o);
        if (lane >= o) x += y;
    }
    if (lane == 31) ws[wid] = x;
    __syncthreads();
    if (tid < 32) {
        int w = (tid < SCAN_B / 32) ? ws[tid] : 0;
        #pragma unroll
        for (int o = 1; o < SCAN_B / 32; o <<= 1) {
            int y = __shfl_up_sync(0xffffffffu, w, o);
            if (tid >= o) w += y;
        }
        if (tid < SCAN_B / 32) ws[tid] = w;
    }
    __syncthreads();
    int pref = wid ? ws[wid - 1] : 0;
    int incl = x + pref;
    if (i < NN) g_rowloc[i] = incl - v;
    if (tid == SCAN_B - 1) g_bsum[blockIdx.x] = incl;
}

__device__ __forceinline__ void block_boff(int* s_boff, int* s_ws) {
    int tid = threadIdx.x;
    if (tid < 128) {
        int lane = tid & 31, w4 = tid >> 5;
        int v = (tid < NBLK) ? g_bsum[tid] : 0;
        int x = v;
        #pragma unroll
        for (int o = 1; o < 32; o <<= 1) {
            int y = __shfl_up_sync(0xffffffffu, x, o);
            if (lane >= o) x += y;
        }
        if (lane == 31) s_ws[w4] = x;
    }
    __syncthreads();
    if (tid < 32) {
        int w = (tid < 4) ? s_ws[tid] : 0;
        #pragma unroll
        for (int o = 1; o < 4; o <<= 1) {
            int y = __shfl_up_sync(0xffffffffu, w, o);
            if (tid >= o) w += y;
        }
        if (tid < 4) s_ws[tid] = w;
    }
    __syncthreads();
    if (tid < 128) {
        int lane = tid & 31, w4 = tid >> 5;
        int v = (tid < NBLK) ? g_bsum[tid] : 0;
        int x = v;
        #pragma unroll
        for (int o = 1; o < 32; o <<= 1) {
            int y = __shfl_up_sync(0xffffffffu, x, o);
            if (lane >= o) x += y;
        }
        int pref = w4 ? s_ws[w4 - 1] : 0;
        if (tid < NBLK) s_boff[tid] = x + pref - v;
    }
    __syncthreads();
}

// ---------------- launch 2: CSR fill + rowptr finalize ----------------
__global__ void fill_finalize_kernel(const int* __restrict__ src, const int* __restrict__ dst) {
    __shared__ int s_boff[NBLK];
    __shared__ int s_ws[4];
    block_boff(s_boff, s_ws);
    int tid = threadIdx.x;
    int b = blockIdx.x;
    if (b < E4_BLOCKS) {
        int i = b * 256 + tid;
        if (i < EE / 4) {
            int4 s = reinterpret_cast<const int4*>(src)[i];
            int4 d = reinterpret_cast<const int4*>(dst)[i];
            int p;
            p = atomicAdd(&g_cursor[d.x], 1); g_csrc[g_rowloc[d.x] + s_boff[d.x >> 9] + p] = s.x;
            p = atomicAdd(&g_cursor[d.y], 1); g_csrc[g_rowloc[d.y] + s_boff[d.y >> 9] + p] = s.y;
            p = atomicAdd(&g_cursor[d.z], 1); g_csrc[g_rowloc[d.z] + s_boff[d.z >> 9] + p] = s.z;
            p = atomicAdd(&g_cursor[d.w], 1); g_csrc[g_rowloc[d.w] + s_boff[d.w >> 9] + p] = s.w;
        }
    } else {
        int i = (b - E4_BLOCKS) * 256 + tid;
        if (i < NN) g_rowptr[i] = g_rowloc[i] + s_boff[i >> 9];
        if (b == E4_BLOCKS && tid == 0) g_rowptr[NN] = EE;
    }
}

// ---------------- SGEMM (FFMA2): output ONLY fp16 shadow (+ optional fused scores) ----------------
// The fp32 product is dead downstream: scores fused here, aggregation gathers fp16.
template<int BN, bool FUSE, bool COUNT>
__global__ __launch_bounds__(256)
void sgemm128_kernel(const float* __restrict__ A, const float* __restrict__ B,
                     const float* __restrict__ avs, const float* __restrict__ avd,
                     const int* __restrict__ edst) {
    if (COUNT && blockIdx.x >= GEMM_BLOCKS) {
        int bi = blockIdx.x - GEMM_BLOCKS;
        int i = bi * 256 + threadIdx.x;
        if (i < EE / 4) {
            int4 d = reinterpret_cast<const int4*>(edst)[i];
            atomicAdd(&g_deg[d.x], 1);
            atomicAdd(&g_deg[d.y], 1);
            atomicAdd(&g_deg[d.z], 1);
            atomicAdd(&g_deg[d.w], 1);
        }
        return;
    }
    constexpr int TN = BN / 16;
    constexpr int TN2 = TN / 2;
    __shared__ float As[16][132];
    __shared__ float Bs[16][BN];
    const int tid = threadIdx.x;
    const int block_row = blockIdx.x * 128;
    const int tr = tid >> 4;
    const int tc = tid & 15;

    unsigned long long acc2[8][TN2];
    #pragma unroll
    for (int i = 0; i < 8; i++)
        #pragma unroll
        for (int j = 0; j < TN2; j++) acc2[i][j] = 0ull;

    const int aRow = tid >> 2;
    const int aCol = (tid & 3) << 2;

    #pragma unroll 2
    for (int k0 = 0; k0 < 128; k0 += 16) {
        #pragma unroll
        for (int i = 0; i < 2; i++) {
            int r = aRow + i * 64;
            int grow = block_row + r;
            float4 v = make_float4(0.f, 0.f, 0.f, 0.f);
            if (grow < NN)
                v = *reinterpret_cast<const float4*>(&A[(size_t)grow * 128 + k0 + aCol]);
            As[aCol + 0][r] = v.x;
            As[aCol + 1][r] = v.y;
            As[aCol + 2][r] = v.z;
            As[aCol + 3][r] = v.w;
        }
        if (BN == 128) {
            #pragma unroll
            for (int i = 0; i < 2; i++) {
                int r = (tid >> 5) + i * 8;
                int c = (tid & 31) * 4;
                *reinterpret_cast<float4*>(&Bs[r][c]) =
                    *reinterpret_cast<const float4*>(&B[(size_t)(k0 + r) * BN + c]);
            }
        } else {
            int r = tid >> 4;
            int c = (tid & 15) * 4;
            *reinterpret_cast<float4*>(&Bs[r][c]) =
                *reinterpret_cast<const float4*>(&B[(size_t)(k0 + r) * BN + c]);
        }
        __syncthreads();
        #pragma unroll
        for (int kk = 0; kk < 16; kk++) {
            float ra[8], rb[TN];
            *reinterpret_cast<float4*>(&ra[0]) = *reinterpret_cast<float4*>(&As[kk][tr * 8]);
            *reinterpret_cast<float4*>(&ra[4]) = *reinterpret_cast<float4*>(&As[kk][tr * 8 + 4]);
            #pragma unroll
            for (int j4 = 0; j4 < TN / 4; j4++)
                *reinterpret_cast<float4*>(&rb[j4 * 4]) =
                    *reinterpret_cast<float4*>(&Bs[kk][tc * TN + j4 * 4]);
            unsigned long long bp[TN2];
            #pragma unroll
            for (int j = 0; j < TN2; j++) bp[j] = pack2(rb[2 * j], rb[2 * j + 1]);
            #pragma unroll
            for (int i = 0; i < 8; i++) {
                unsigned long long ap = pack2(ra[i], ra[i]);
                #pragma unroll
                for (int j = 0; j < TN2; j++)
                    fma2(acc2[i][j], ap, bp[j]);
            }
        }
        __syncthreads();
    }

    float acc[8][TN];
    #pragma unroll
    for (int i = 0; i < 8; i++)
        #pragma unroll
        for (int j = 0; j < TN2; j++)
            unpack2(acc2[i][j], acc[i][2 * j], acc[i][2 * j + 1]);

    // fp16-only epilogue store
    #pragma unroll
    for (int i = 0; i < 8; i++) {
        int grow = block_row + tr * 8 + i;
        if (grow < NN) {
            __half2 hp[TN2];
            #pragma unroll
            for (int j = 0; j < TN2; j++)
                hp[j] = __floats2half2_rn(acc[i][2 * j], acc[i][2 * j + 1]);
            if (TN == 8)
                *reinterpret_cast<uint4*>(&g_h16[(size_t)grow * BN + tc * TN]) =
                    *reinterpret_cast<uint4*>(hp);
            else
                *reinterpret_cast<uint2*>(&g_h16[(size_t)grow * BN + tc * TN]) =
                    *reinterpret_cast<uint2*>(hp);
        }
    }

    if (FUSE) {
        float avsr[TN], avdr[TN];
        #pragma unroll
        for (int j = 0; j < TN; j++) {
            avsr[j] = avs[tc * TN + j];
            avdr[j] = avd[tc * TN + j];
        }
        #pragma unroll
        for (int i = 0; i < 8; i++) {
            float s = 0.f, d = 0.f;
            #pragma unroll
            for (int j = 0; j < TN; j++) {
                s = fmaf(acc[i][j], avsr[j], s);
                d = fmaf(acc[i][j], avdr[j], d);
            }
            #pragma unroll
            for (int mk = 1; mk < 16; mk <<= 1) {
                s += __shfl_xor_sync(0xffffffffu, s, mk);
                d += __shfl_xor_sync(0xffffffffu, d, mk);
            }
            if (tc == 0) {
                int grow = block_row + tr * 8 + i;
                if (grow < NN) { g_as[grow] = s; g_ad[grow] = d; }
            }
        }
    }
}

// ---------------- GAT aggregate: single fused pass, fp16 row gather ----------------
// Softmax shift-invariance: scores ~N(0,~2), no overflow risk without max-subtract.
__global__ __launch_bounds__(256)
void gat_agg_kernel(const float* __restrict__ bias,
                    float* __restrict__ out) {
    int warp = (blockIdx.x * blockDim.x + threadIdx.x) >> 5;
    int lane = threadIdx.x & 31;
    if (warp >= NN) return;
    int node = warp;
    int rs = g_rowptr[node], re = g_rowptr[node + 1];
    float adi = g_ad[node];
    float pself = __expf(lrelu(g_as[node] + adi));

    const uint2* h2 = reinterpret_cast<const uint2*>(g_h16);   // 4 halves per lane
    uint2 selfraw = h2[(size_t)node * 32 + lane];
    float2 sf01 = __half22float2(*reinterpret_cast<__half2*>(&selfraw.x));
    float2 sf23 = __half22float2(*reinterpret_cast<__half2*>(&selfraw.y));
    float4 acc = make_float4(pself * sf01.x, pself * sf01.y, pself * sf23.x, pself * sf23.y);
    float ssum_l = (lane == 0) ? pself : 0.f;

    for (int base = rs; base < re; base += 32) {
        int j = base + lane;
        int srcv = 0; float pv = 0.f;
        if (j < re) {
            srcv = g_csrc[j];
            pv = __expf(lrelu(g_as[srcv] + adi));
        }
        ssum_l += pv;
        int cnt = re - base;
        if (cnt >= 32) {
            #pragma unroll
            for (int t = 0; t < 32; t++) {
                int s = __shfl_sync(0xffffffffu, srcv, t);
                float p = __shfl_sync(0xffffffffu, pv, t);
                uint2 raw = h2[(size_t)s * 32 + lane];
                float2 f01 = __half22float2(*reinterpret_cast<__half2*>(&raw.x));
                float2 f23 = __half22float2(*reinterpret_cast<__half2*>(&raw.y));
                acc.x = fmaf(p, f01.x, acc.x);
                acc.y = fmaf(p, f01.y, acc.y);
                acc.z = fmaf(p, f23.x, acc.z);
                acc.w = fmaf(p, f23.y, acc.w);
            }
        } else {
            for (int t = 0; t < cnt; t++) {
                int s = __shfl_sync(0xffffffffu, srcv, t);
                float p = __shfl_sync(0xffffffffu, pv, t);
                uint2 raw = h2[(size_t)s * 32 + lane];
                float2 f01 = __half22float2(*reinterpret_cast<__half2*>(&raw.x));
                float2 f23 = __half22float2(*reinterpret_cast<__half2*>(&raw.y));
                acc.x = fmaf(p, f01.x, acc.x);
                acc.y = fmaf(p, f01.y, acc.y);
                acc.z = fmaf(p, f23.x, acc.z);
                acc.w = fmaf(p, f23.y, acc.w);
            }
        }
    }
    float ssum = ssum_l;
    #pragma unroll
    for (int o = 16; o; o >>= 1) ssum += __shfl_xor_sync(0xffffffffu, ssum, o);

    float inv = 1.f / ssum;
    float4 bv = reinterpret_cast<const float4*>(bias)[lane];
    float4 o;
    o.x = fmaxf(fmaf(acc.x, inv, bv.x), 0.f);
    o.y = fmaxf(fmaf(acc.y, inv, bv.y), 0.f);
    o.z = fmaxf(fmaf(acc.z, inv, bv.z), 0.f);
    o.w = fmaxf(fmaf(acc.w, inv, bv.w), 0.f);
    reinterpret_cast<float4*>(out)[(size_t)node * 32 + lane] = o;
}

// ---------------- GCN aggregate: fp16 gather (4 B/lane/edge), OUT=64 ----------------
__global__ __launch_bounds__(256)
void gcn_agg_kernel(const float* __restrict__ bias,
                    float* __restrict__ z) {
    int warp = (blockIdx.x * blockDim.x + threadIdx.x) >> 5;
    int lane = threadIdx.x & 31;
    if (warp >= NN) return;
    int node = warp;
    int rs = g_rowptr[node], re = g_rowptr[node + 1];
    float di = g_dinv[node];
    const unsigned int* h1 = reinterpret_cast<const unsigned int*>(g_h16); // 2 halves/lane
    unsigned int selfraw = h1[(size_t)node * 32 + lane];
    float2 gv = __half22float2(*reinterpret_cast<__half2*>(&selfraw));
    float nself = di * di;
    float2 acc = make_float2(nself * gv.x, nself * gv.y);
    for (int base = rs; base < re; base += 32) {
        int j = base + lane;
        int srcv = 0; float dv = 0.f;
        if (j < re) { srcv = g_csrc[j]; dv = g_dinv[srcv]; }
        int cnt = re - base;
        if (cnt >= 32) {
            #pragma unroll
            for (int t = 0; t < 32; t++) {
                int s = __shfl_sync(0xffffffffu, srcv, t);
                float nd = __shfl_sync(0xffffffffu, dv, t);
                float nrm = di * nd;
                unsigned int raw = h1[(size_t)s * 32 + lane];
                float2 v = __half22float2(*reinterpret_cast<__half2*>(&raw));
                acc.x = fmaf(nrm, v.x, acc.x);
                acc.y = fmaf(nrm, v.y, acc.y);
            }
        } else {
            for (int t = 0; t < cnt; t++) {
                int s = __shfl_sync(0xffffffffu, srcv, t);
                float nd = __shfl_sync(0xffffffffu, dv, t);
                float nrm = di * nd;
                unsigned int raw = h1[(size_t)s * 32 + lane];
                float2 v = __half22float2(*reinterpret_cast<__half2*>(&raw));
                acc.x = fmaf(nrm, v.x, acc.x);
                acc.y = fmaf(nrm, v.y, acc.y);
            }
        }
    }
    float2 bv = reinterpret_cast<const float2*>(bias)[lane];
    reinterpret_cast<float2*>(z)[(size_t)node * 32 + lane] =
        make_float2(acc.x + bv.x, acc.y + bv.y);
}

// ---------------- decode + re-zero of deg/cursor ----------------
__global__ void decode_kernel(const int* __restrict__ eli, float* __restrict__ out) {
    if (blockIdx.x >= DEC_BLOCKS) {
        int i = (blockIdx.x - DEC_BLOCKS) * 256 + threadIdx.x;
        for (int k = i; k < NN; k += ZERO_BLOCKS * 256) { g_deg[k] = 0; g_cursor[k] = 0; }
        return;
    }
    int gtid = blockIdx.x * blockDim.x + threadIdx.x;
    int warp = gtid >> 5;
    int lane = threadIdx.x & 31;
    int sub = lane >> 3, l8 = lane & 7;
    int e = warp * 4 + sub;
    if (e >= NLL) return;
    int a = eli[e];
    int b = eli[NLL + e];
    const float4* z4 = reinterpret_cast<const float4*>(g_zbuf);
    float4 va0 = z4[(size_t)a * 16 + l8];
    float4 va1 = z4[(size_t)a * 16 + 8 + l8];
    float4 vb0 = z4[(size_t)b * 16 + l8];
    float4 vb1 = z4[(size_t)b * 16 + 8 + l8];
    float dot = va0.x * vb0.x + va0.y * vb0.y + va0.z * vb0.z + va0.w * vb0.w
              + va1.x * vb1.x + va1.y * vb1.y + va1.z * vb1.z + va1.w * vb1.w;
    dot += __shfl_xor_sync(0xffffffffu, dot, 4);
    dot += __shfl_xor_sync(0xffffffffu, dot, 2);
    dot += __shfl_xor_sync(0xffffffffu, dot, 1);
    if (l8 == 0) out[e] = dot;
}

// ---------------- launch ----------------
extern "C" void kernel_launch(void* const* d_in, const int* in_sizes, int n_in,
                              void* d_out, int out_size) {
    const float* x   = (const float*)d_in[0];
    const int*   ei  = (const int*)d_in[1];          // [2,E]
    const int*   eli = (const int*)d_in[2];          // [2,NL]
    const float* W1  = (const float*)d_in[3];
    const float* a1s = (const float*)d_in[4];
    const float* a1d = (const float*)d_in[5];
    const float* b1  = (const float*)d_in[6];
    const float* W2  = (const float*)d_in[7];
    const float* a2s = (const float*)d_in[8];
    const float* a2d = (const float*)d_in[9];
    const float* b2  = (const float*)d_in[10];
    const float* W3  = (const float*)d_in[11];
    const float* a3s = (const float*)d_in[12];
    const float* a3d = (const float*)d_in[13];
    const float* b3  = (const float*)d_in[14];
    const float* W4  = (const float*)d_in[15];
    const float* b4  = (const float*)d_in[16];
    float* out = (float*)d_out;

    const int* e_src = ei;
    const int* e_dst = ei + EE;

    float *bufB, *zbuf;
    cudaGetSymbolAddress((void**)&bufB, g_bufB);
    cudaGetSymbolAddress((void**)&zbuf, g_zbuf);

    const int TB = 256;
    int node_warp_blocks = (NN * 32 + TB - 1) / TB;

    // 0: sgemm1 + fused degree-count (writes h16 + scores only)
    sgemm128_kernel<HIDD, true, true><<<GEMM_BLOCKS + E4_BLOCKS, 256>>>(x, W1, a1s, a1d, e_dst);
    // 1: per-block local scan (+dinv, +bsum)
    scan_partial_kernel<<<NBLK, SCAN_B>>>();
    // 2: CSR fill + rowptr finalize
    fill_finalize_kernel<<<E4_BLOCKS + FIN_BLOCKS, TB>>>(e_src, e_dst);
    // 3: gat layer 1  <- profiled launch index
    gat_agg_kernel<<<node_warp_blocks, TB>>>(b1, bufB);

    // layer 2
    sgemm128_kernel<HIDD, true, false><<<GEMM_BLOCKS, 256>>>(bufB, W2, a2s, a2d, nullptr);
    gat_agg_kernel<<<node_warp_blocks, TB>>>(b2, bufB);

    // layer 3
    sgemm128_kernel<HIDD, true, false><<<GEMM_BLOCKS, 256>>>(bufB, W3, a3s, a3d, nullptr);
    gat_agg_kernel<<<node_warp_blocks, TB>>>(b3, bufB);

    // GCN
    sgemm128_kernel<DOUT, false, false><<<GEMM_BLOCKS, 256>>>(bufB, W4, nullptr, nullptr, nullptr);
    gcn_agg_kernel<<<node_warp_blocks, TB>>>(b4, zbuf);

    // decode + re-zero deg/cursor
    decode_kernel<<<DEC_BLOCKS + ZERO_BLOCKS, TB>>>(eli, out);
}